// round 2
// baseline (speedup 1.0000x reference)
#include <cuda_runtime.h>
#include <cuda_bf16.h>
#include <cstdint>

// Problem dims (fixed for this problem instance)
#define K_DIM 2048
#define M_DIM 16384   // B*S = 4*4096
#define N_DIM 8192

// ---------------- scratch (static device memory; no allocation) ----------------
__device__ float g_partials[2048];
__device__ float g_wscale;
__device__ float g_row_inv[M_DIM];                         // amax/127 per row
__device__ __nv_bfloat16 g_qx[(size_t)M_DIM * K_DIM];      // quantized activations (ints in bf16)
__device__ __nv_bfloat16 g_wt[(size_t)N_DIM * K_DIM];      // ternary weights in bf16

__device__ __forceinline__ uint32_t smem_u32(const void* p) {
    return (uint32_t)__cvta_generic_to_shared(p);
}

// ---------------- weight abs-mean: partial sums ----------------
__global__ void wabs_partial(const float* __restrict__ w) {
    const float4* w4 = (const float4*)w;
    const int n4 = (N_DIM * K_DIM) / 4;
    float s = 0.f;
    for (int i = blockIdx.x * blockDim.x + threadIdx.x; i < n4; i += gridDim.x * blockDim.x) {
        float4 v = w4[i];
        s += fabsf(v.x) + fabsf(v.y) + fabsf(v.z) + fabsf(v.w);
    }
    __shared__ float sh[256];
    sh[threadIdx.x] = s;
    __syncthreads();
    for (int o = 128; o > 0; o >>= 1) {
        if (threadIdx.x < o) sh[threadIdx.x] += sh[threadIdx.x + o];
        __syncthreads();
    }
    if (threadIdx.x == 0) g_partials[blockIdx.x] = sh[0];
}

__global__ void wabs_final() {
    __shared__ float sh[256];
    float s = 0.f;
    for (int i = threadIdx.x; i < 2048; i += 256) s += g_partials[i];
    sh[threadIdx.x] = s;
    __syncthreads();
    for (int o = 128; o > 0; o >>= 1) {
        if (threadIdx.x < o) sh[threadIdx.x] += sh[threadIdx.x + o];
        __syncthreads();
    }
    if (threadIdx.x == 0) {
        float m = sh[0] / (float)((size_t)N_DIM * K_DIM);
        g_wscale = fmaxf(m, 1e-8f);
    }
}

// ---------------- ternary weight quantization ----------------
__global__ void wquant(const float* __restrict__ w) {
    const float inv = 1.0f / g_wscale;
    const float4* w4 = (const float4*)w;
    const int n4 = (N_DIM * K_DIM) / 4;
    for (int i = blockIdx.x * blockDim.x + threadIdx.x; i < n4; i += gridDim.x * blockDim.x) {
        float4 v = w4[i];
        float q0 = fminf(fmaxf(rintf(v.x * inv), -1.f), 1.f);
        float q1 = fminf(fmaxf(rintf(v.y * inv), -1.f), 1.f);
        float q2 = fminf(fmaxf(rintf(v.z * inv), -1.f), 1.f);
        float q3 = fminf(fmaxf(rintf(v.w * inv), -1.f), 1.f);
        __nv_bfloat162 p0 = __floats2bfloat162_rn(q0, q1);
        __nv_bfloat162 p1 = __floats2bfloat162_rn(q2, q3);
        uint2 pk;
        pk.x = *(uint32_t*)&p0;
        pk.y = *(uint32_t*)&p1;
        ((uint2*)g_wt)[i] = pk;
    }
}

// ---------------- fused RMS-norm + activation quantization (one block per row) ----------------
__global__ __launch_bounds__(256) void act_quant(const float* __restrict__ x,
                                                 const float* __restrict__ gamma) {
    const int row = blockIdx.x;
    const int t = threadIdx.x;
    const float4* xr = (const float4*)(x + (size_t)row * K_DIM);
    const float4* g4 = (const float4*)gamma;

    float4 v0 = xr[t];
    float4 v1 = xr[t + 256];

    float ss = v0.x * v0.x + v0.y * v0.y + v0.z * v0.z + v0.w * v0.w
             + v1.x * v1.x + v1.y * v1.y + v1.z * v1.z + v1.w * v1.w;

    __shared__ float sh[256];
    sh[t] = ss;
    __syncthreads();
    for (int o = 128; o > 0; o >>= 1) {
        if (t < o) sh[t] += sh[t + o];
        __syncthreads();
    }
    const float r = rsqrtf(sh[0] / (float)K_DIM + 1e-6f);
    __syncthreads();

    float4 gm0 = g4[t];
    float4 gm1 = g4[t + 256];

    float xn[8];
    xn[0] = v0.x * r * gm0.x; xn[1] = v0.y * r * gm0.y;
    xn[2] = v0.z * r * gm0.z; xn[3] = v0.w * r * gm0.w;
    xn[4] = v1.x * r * gm1.x; xn[5] = v1.y * r * gm1.y;
    xn[6] = v1.z * r * gm1.z; xn[7] = v1.w * r * gm1.w;

    float am = 0.f;
#pragma unroll
    for (int i = 0; i < 8; i++) am = fmaxf(am, fabsf(xn[i]));
    sh[t] = am;
    __syncthreads();
    for (int o = 128; o > 0; o >>= 1) {
        if (t < o) sh[t] = fmaxf(sh[t], sh[t + o]);
        __syncthreads();
    }
    const float amax = fmaxf(sh[0], 1e-5f);
    const float scale = 127.0f / amax;
    if (t == 0) g_row_inv[row] = amax / 127.0f;

    float q[8];
#pragma unroll
    for (int i = 0; i < 8; i++)
        q[i] = fminf(fmaxf(rintf(xn[i] * scale), -128.f), 127.f);

    __nv_bfloat16* dst = g_qx + (size_t)row * K_DIM;
    {
        __nv_bfloat162 p0 = __floats2bfloat162_rn(q[0], q[1]);
        __nv_bfloat162 p1 = __floats2bfloat162_rn(q[2], q[3]);
        uint2 pk; pk.x = *(uint32_t*)&p0; pk.y = *(uint32_t*)&p1;
        ((uint2*)dst)[t] = pk;
    }
    {
        __nv_bfloat162 p0 = __floats2bfloat162_rn(q[4], q[5]);
        __nv_bfloat162 p1 = __floats2bfloat162_rn(q[6], q[7]);
        uint2 pk; pk.x = *(uint32_t*)&p0; pk.y = *(uint32_t*)&p1;
        ((uint2*)dst)[t + 256] = pk;
    }
}

// ---------------- GEMM: out[m,n] = (sum_k qx[m,k] * wt[n,k]) * row_inv[m] ----------------
// bf16 HMMA m16n8k16, 128x128x32 block tile, 8 warps (2m x 4n), cp.async double buffer.
#define BM 128
#define BN 128
#define BK 32
#define PAD 40  // bf16 row stride in smem (80 bytes: 16B-aligned, conflict-free for ldmatrix)

__global__ __launch_bounds__(256) void gemm_bf16(float* __restrict__ out) {
    __shared__ __nv_bfloat16 sA[2][BM * PAD];
    __shared__ __nv_bfloat16 sB[2][BN * PAD];

    const int tid = threadIdx.x;
    const int bm = blockIdx.y * BM;
    const int bn = blockIdx.x * BN;
    const __nv_bfloat16* Ag = g_qx + (size_t)bm * K_DIM;
    const __nv_bfloat16* Bg = g_wt + (size_t)bn * K_DIM;

    const int warp = tid >> 5;
    const int lane = tid & 31;
    const int wm = (warp >> 2) * 64;  // 0 or 64
    const int wn = (warp & 3) * 32;   // 0,32,64,96

    float acc[4][4][4];
#pragma unroll
    for (int i = 0; i < 4; i++)
#pragma unroll
        for (int j = 0; j < 4; j++)
#pragma unroll
            for (int l = 0; l < 4; l++) acc[i][j][l] = 0.f;

    auto load_tile = [&](int buf, int kt) {
        const int k0 = kt * BK;
#pragma unroll
        for (int i = 0; i < 2; i++) {
            int chunk = tid + i * 256;      // 0..511
            int row = chunk >> 2;           // 0..127
            int c = (chunk & 3) * 8;        // 0,8,16,24 (bf16)
            uint32_t sa = smem_u32(&sA[buf][row * PAD + c]);
            const void* ga = Ag + (size_t)row * K_DIM + k0 + c;
            asm volatile("cp.async.cg.shared.global [%0], [%1], 16;\n" ::"r"(sa), "l"(ga));
            uint32_t sb = smem_u32(&sB[buf][row * PAD + c]);
            const void* gb = Bg + (size_t)row * K_DIM + k0 + c;
            asm volatile("cp.async.cg.shared.global [%0], [%1], 16;\n" ::"r"(sb), "l"(gb));
        }
    };

    const int T = K_DIM / BK;  // 64
    load_tile(0, 0);
    asm volatile("cp.async.commit_group;\n");

    for (int t = 0; t < T; t++) {
        const int cur = t & 1;
        if (t + 1 < T) {
            load_tile((t + 1) & 1, t + 1);
            asm volatile("cp.async.commit_group;\n");
            asm volatile("cp.async.wait_group 1;\n");
        } else {
            asm volatile("cp.async.wait_group 0;\n");
        }
        __syncthreads();

#pragma unroll
        for (int ks = 0; ks < 2; ks++) {
            const int k0 = ks * 16;
            uint32_t a[4][4];
#pragma unroll
            for (int mf = 0; mf < 4; mf++) {
                int r = wm + mf * 16 + (lane & 15);
                int c = k0 + (lane >> 4) * 8;
                uint32_t addr = smem_u32(&sA[cur][r * PAD + c]);
                asm volatile("ldmatrix.sync.aligned.m8n8.x4.shared.b16 {%0,%1,%2,%3}, [%4];\n"
                             : "=r"(a[mf][0]), "=r"(a[mf][1]), "=r"(a[mf][2]), "=r"(a[mf][3])
                             : "r"(addr));
            }
            uint32_t b[4][2];
#pragma unroll
            for (int nfp = 0; nfp < 2; nfp++) {
                int r = wn + nfp * 16 + ((lane >> 4) & 1) * 8 + (lane & 7);
                int c = k0 + ((lane >> 3) & 1) * 8;
                uint32_t addr = smem_u32(&sB[cur][r * PAD + c]);
                uint32_t b0, b1, b2, b3;
                asm volatile("ldmatrix.sync.aligned.m8n8.x4.shared.b16 {%0,%1,%2,%3}, [%4];\n"
                             : "=r"(b0), "=r"(b1), "=r"(b2), "=r"(b3)
                             : "r"(addr));
                b[nfp * 2][0] = b0;
                b[nfp * 2][1] = b1;
                b[nfp * 2 + 1][0] = b2;
                b[nfp * 2 + 1][1] = b3;
            }
#pragma unroll
            for (int mf = 0; mf < 4; mf++) {
#pragma unroll
                for (int nf = 0; nf < 4; nf++) {
                    asm volatile(
                        "mma.sync.aligned.m16n8k16.row.col.f32.bf16.bf16.f32 "
                        "{%0,%1,%2,%3}, {%4,%5,%6,%7}, {%8,%9}, {%0,%1,%2,%3};\n"
                        : "+f"(acc[mf][nf][0]), "+f"(acc[mf][nf][1]),
                          "+f"(acc[mf][nf][2]), "+f"(acc[mf][nf][3])
                        : "r"(a[mf][0]), "r"(a[mf][1]), "r"(a[mf][2]), "r"(a[mf][3]),
                          "r"(b[nf][0]), "r"(b[nf][1]));
                }
            }
        }
        __syncthreads();
    }

    // epilogue: scale by per-row inv and store
#pragma unroll
    for (int mf = 0; mf < 4; mf++) {
        int r0 = bm + wm + mf * 16 + (lane >> 2);
        float s0 = g_row_inv[r0];
        float s1 = g_row_inv[r0 + 8];
#pragma unroll
        for (int nf = 0; nf < 4; nf++) {
            int c0 = bn + wn + nf * 8 + (lane & 3) * 2;
            float2 v0 = make_float2(acc[mf][nf][0] * s0, acc[mf][nf][1] * s0);
            float2 v1 = make_float2(acc[mf][nf][2] * s1, acc[mf][nf][3] * s1);
            *(float2*)(out + (size_t)r0 * N_DIM + c0) = v0;
            *(float2*)(out + (size_t)(r0 + 8) * N_DIM + c0) = v1;
        }
    }
}

// ---------------- launcher ----------------
extern "C" void kernel_launch(void* const* d_in, const int* in_sizes, int n_in,
                              void* d_out, int out_size) {
    const float* x = (const float*)d_in[0];
    const float* w = (const float*)d_in[1];
    const float* gamma = (const float*)d_in[2];
    float* out = (float*)d_out;

    wabs_partial<<<2048, 256>>>(w);
    wabs_final<<<1, 256>>>();
    wquant<<<4096, 256>>>(w);
    act_quant<<<M_DIM, 256>>>(x, gamma);

    dim3 grid(N_DIM / BN, M_DIM / BM);
    gemm_bf16<<<grid, 256>>>(out);
}